// round 7
// baseline (speedup 1.0000x reference)
#include <cuda_runtime.h>
#include <cuda_fp16.h>
#include <math.h>

#define BATCH 8
#define HP 256        // pooled H/W
#define HF 512        // full H/W

// Scratch (device globals — no allocation allowed)
__device__ float g_pool[2][BATCH][HP][HP];        // pooled fixed, moved (4MB)
__device__ __half g_diff[BATCH * 8][HP][HP];      // mind descriptor diff (8MB, fp16)
__device__ unsigned int g_hist_part[BATCH][32][256];
__device__ unsigned int g_hist_agg[BATCH][256];
__device__ float g_part_mind[1024];
__device__ float g_part_reg[512];
__device__ unsigned int g_done;                   // zero-init; self-resets each run

__device__ __forceinline__ float san(float v) { return (v == v) ? v : 0.0f; }
__device__ __forceinline__ int clampi(int v, int lo, int hi) { return min(max(v, lo), hi); }

// ============ fused front-end: pool fixed (+hist), pool moved, flow regularizer ====
__global__ __launch_bounds__(256) void k_front(const float* __restrict__ fixed,
                                               const float* __restrict__ moved,
                                               const float* __restrict__ flow) {
    int blk = blockIdx.x;
    int t = threadIdx.x;

    if (blk < 512) {
        int p = blk >> 8;            // 0 fixed, 1 moved
        int b = (blk >> 5) & 7;
        int st = blk & 31;           // 8 pooled rows per strip
        int tt = t & 127;            // float4 col group -> pooled cols 2tt, 2tt+1
        int half = t >> 7;
        const float* src = (p == 0 ? fixed : moved) + (size_t)b * HF * HF;
        const float* msrc = moved + (size_t)b * HF * HF;

        __shared__ unsigned int sh[256];
        if (p == 0) {
            sh[t] = 0u;
            __syncthreads();
        }

        #pragma unroll
        for (int j = 0; j < 4; j++) {
            int y = st * 8 + half * 4 + j;
            const float4* r0 = (const float4*)(src + (size_t)(2 * y) * HF) + tt;
            float4 a = r0[0];
            float4 c = r0[HF / 4];
            float p0 = 0.25f * (san(a.x) + san(a.y) + san(c.x) + san(c.y));
            float p1 = 0.25f * (san(a.z) + san(a.w) + san(c.z) + san(c.w));
            ((float2*)&g_pool[p][b][y][0])[tt] = make_float2(p0, p1);
            if (p == 0) {
                float4 m = ((const float4*)(msrc + (size_t)(2 * y) * HF))[tt];
                // samples (2y,4tt) and (2y,4tt+2); searchsorted-left == ceil(v*16)-1
                float xf0 = fminf(fmaxf((san(a.x) + 1.0f) * 0.5f, 0.001f), 0.999f);
                float yf0 = fminf(fmaxf((san(m.x) + 1.0f) * 0.5f, 0.001f), 0.999f);
                int xb0 = clampi((int)ceilf(xf0 * 16.0f) - 1, 0, 15);
                int yb0 = clampi((int)ceilf(yf0 * 16.0f) - 1, 0, 15);
                atomicAdd(&sh[xb0 * 16 + yb0], 1u);
                float xf1 = fminf(fmaxf((san(a.z) + 1.0f) * 0.5f, 0.001f), 0.999f);
                float yf1 = fminf(fmaxf((san(m.z) + 1.0f) * 0.5f, 0.001f), 0.999f);
                int xb1 = clampi((int)ceilf(xf1 * 16.0f) - 1, 0, 15);
                int yb1 = clampi((int)ceilf(yf1 * 16.0f) - 1, 0, 15);
                atomicAdd(&sh[xb1 * 16 + yb1], 1u);
            }
        }
        if (p == 0) {
            __syncthreads();
            g_hist_part[b][st][t] = sh[t];
        }
    } else {
        // ---- regularizer: fused pool of flow + sobel/laplacian, 4 rows per block ----
        int q = blk - 512;
        int b = q >> 6;
        int st = q & 63;
        int tt = t & 127;
        int sel = t >> 7;    // 0 -> u, 1 -> v
        const float* base = flow + ((size_t)b * 2 + sel) * HF * HF;

        __shared__ float su[6][256];
        __shared__ float sv[6][256];
        float (*sbuf)[256] = sel ? sv : su;

        #pragma unroll
        for (int r = 0; r < 6; r++) {
            int py = clampi(st * 4 - 1 + r, 0, HP - 1);
            const float4* q0 = (const float4*)(base + (size_t)(2 * py) * HF) + tt;
            float4 a = q0[0];
            float4 c = q0[HF / 4];
            sbuf[r][2 * tt]     = 0.25f * (san(a.x) + san(a.y) + san(c.x) + san(c.y));
            sbuf[r][2 * tt + 1] = 0.25f * (san(a.z) + san(a.w) + san(c.z) + san(c.w));
        }
        __syncthreads();

        int xm = max(t - 1, 0), xp = min(t + 1, HP - 1);
        float acc = 0.f;
        #pragma unroll
        for (int j = 0; j < 4; j++) {
            int r = j + 1;
            float u00 = su[r - 1][xm], u01 = su[r - 1][t], u02 = su[r - 1][xp];
            float u10 = su[r][xm],     u11 = su[r][t],     u12 = su[r][xp];
            float u20 = su[r + 1][xm], u21 = su[r + 1][t], u22 = su[r + 1][xp];
            float v00 = sv[r - 1][xm], v01 = sv[r - 1][t], v02 = sv[r - 1][xp];
            float v10 = sv[r][xm],     v11 = sv[r][t],     v12 = sv[r][xp];
            float v20 = sv[r + 1][xm], v21 = sv[r + 1][t], v22 = sv[r + 1][xp];

            float gxu = (u02 + 2.f * u12 + u22) - (u00 + 2.f * u10 + u20);
            float gyu = (u20 + 2.f * u21 + u22) - (u00 + 2.f * u01 + u02);
            float lpu = u01 + u10 + u12 + u21 - 4.f * u11;
            float gxv = (v02 + 2.f * v12 + v22) - (v00 + 2.f * v10 + v20);
            float gyv = (v20 + 2.f * v21 + v22) - (v00 + 2.f * v01 + v02);
            float lpv = v01 + v10 + v12 + v21 - 4.f * v11;

            float gm = gxu * gxu + gyu * gyu + gxv * gxv + gyv * gyv;
            float lm = lpu * lpu + lpv * lpv;
            acc += fminf(gm, 100.0f) + fminf(lm, 100.0f);
        }

        __shared__ float red[256];
        red[t] = acc;
        __syncthreads();
        #pragma unroll
        for (int s = 128; s > 0; s >>= 1) {
            if (t < s) red[t] += red[t + s];
            __syncthreads();
        }
        if (t == 0) g_part_reg[q] = red[0];
    }
}

// ---------------- MIND descriptors for both images, write diff (fp16) ----------------
#define BX 32
#define BY 16
#define SW 38   // BX + 6
__global__ __launch_bounds__(512) void k_mind() {
    __shared__ float sF[BY + 6][SW];
    __shared__ float sM[BY + 6][SW];
    __shared__ float hF[BY + 4][BX + 2];
    __shared__ float hM[BY + 4][BX + 2];
    __shared__ float vF[BY + 2][BX + 2];
    __shared__ float vM[BY + 2][BX + 2];
    __shared__ float hvF[BY + 2][BX];
    __shared__ float hvM[BY + 2][BX];

    int b = blockIdx.z;
    int tileX = blockIdx.x * BX, tileY = blockIdx.y * BY;
    int gx0 = tileX - 3, gy0 = tileY - 3;
    int tid = threadIdx.y * BX + threadIdx.x;
    int ty = threadIdx.y, tx = threadIdx.x;
    const float* imF = &g_pool[0][b][0][0];
    const float* imM = &g_pool[1][b][0][0];

    bool interior = (blockIdx.x >= 1) && (blockIdx.x <= 6) &&
                    (blockIdx.y >= 1) && (blockIdx.y <= 14);

    const int offdx[8] = {-2, -2, -2, 0, 0, 2, 2, 2};
    const int offdy[8] = {-2, 0, 2, -2, 2, -2, 0, 2};

    float cF, cM, invF, invM;

    if (interior) {
        for (int s = tid; s < (BY + 6) * SW; s += 512) {
            int sy = s / SW, sx = s % SW;
            sF[sy][sx] = imF[(gy0 + sy) * HP + gx0 + sx];
            sM[sy][sx] = imM[(gy0 + sy) * HP + gx0 + sx];
        }
        __syncthreads();

        for (int s = tid; s < (BY + 4) * (BX + 2); s += 512) {
            int sy = s / (BX + 2), sx = s % (BX + 2);
            hF[sy][sx] = sF[sy][sx] + sF[sy][sx + 1] + sF[sy][sx + 2];
            hM[sy][sx] = sM[sy][sx] + sM[sy][sx + 1] + sM[sy][sx + 2];
        }
        __syncthreads();

        for (int s = tid; s < (BY + 2) * (BX + 2); s += 512) {
            int sy = s / (BX + 2), sx = s % (BX + 2);
            float pmF = hF[sy][sx] + hF[sy + 1][sx] + hF[sy + 2][sx];
            float pmM = hM[sy][sx] + hM[sy + 1][sx] + hM[sy + 2][sx];
            float dF = sF[sy + 2][sx + 2] - pmF * (1.0f / 9.0f);
            float dM = sM[sy + 2][sx + 2] - pmM * (1.0f / 9.0f);
            vF[sy][sx] = dF * dF;
            vM[sy][sx] = dM * dM;
        }
        __syncthreads();

        for (int s = tid; s < (BY + 2) * BX; s += 512) {
            int sy = s >> 5, sx = s & 31;
            hvF[sy][sx] = vF[sy][sx] + vF[sy][sx + 1] + vF[sy][sx + 2];
            hvM[sy][sx] = vM[sy][sx] + vM[sy][sx + 1] + vM[sy][sx + 2];
        }
        __syncthreads();

        float varF = fmaxf((hvF[ty][tx] + hvF[ty + 1][tx] + hvF[ty + 2][tx]) * (1.0f / 9.0f), 1e-4f);
        float varM = fmaxf((hvM[ty][tx] + hvM[ty + 1][tx] + hvM[ty + 2][tx]) * (1.0f / 9.0f), 1e-4f);
        invF = 1.0f / (varF * 2.0f + 1e-6f);
        invM = 1.0f / (varM * 2.0f + 1e-6f);
        cF = sF[ty + 3][tx + 3];
        cM = sM[ty + 3][tx + 3];
    } else {
        for (int s = tid; s < (BY + 6) * SW; s += 512) {
            int sy = s / SW, sx = s % SW;
            int gy = clampi(gy0 + sy, 0, HP - 1);
            int gx = clampi(gx0 + sx, 0, HP - 1);
            sF[sy][sx] = imF[gy * HP + gx];
            sM[sy][sx] = imM[gy * HP + gx];
        }
        __syncthreads();

        for (int s = tid; s < (BY + 2) * (BX + 2); s += 512) {
            int sy = s / (BX + 2), sx = s % (BX + 2);
            int uc = clampi(tileY - 1 + sy, 0, HP - 1);
            int vc = clampi(tileX - 1 + sx, 0, HP - 1);
            float pmF = 0.f, pmM = 0.f;
            #pragma unroll
            for (int a = 0; a < 3; a++) {
                int rr = clampi(uc - 2 + a, 0, HP - 1) - gy0;
                #pragma unroll
                for (int bb = 0; bb < 3; bb++) {
                    int cc = clampi(vc - 2 + bb, 0, HP - 1) - gx0;
                    pmF += sF[rr][cc];
                    pmM += sM[rr][cc];
                }
            }
            float dF = sF[uc - gy0][vc - gx0] - pmF * (1.0f / 9.0f);
            float dM = sM[uc - gy0][vc - gx0] - pmM * (1.0f / 9.0f);
            vF[sy][sx] = dF * dF;
            vM[sy][sx] = dM * dM;
        }
        __syncthreads();

        int y = tileY + ty, x = tileX + tx;
        float vsF = 0.f, vsM = 0.f;
        #pragma unroll
        for (int a = -1; a <= 1; a++) {
            int rr = clampi(y + a, 0, HP - 1) - (tileY - 1);
            #pragma unroll
            for (int bb = -1; bb <= 1; bb++) {
                int cc = clampi(x + bb, 0, HP - 1) - (tileX - 1);
                vsF += vF[rr][cc];
                vsM += vM[rr][cc];
            }
        }
        float varF = fmaxf(vsF * (1.0f / 9.0f), 1e-4f);
        float varM = fmaxf(vsM * (1.0f / 9.0f), 1e-4f);
        invF = 1.0f / (varF * 2.0f + 1e-6f);
        invM = 1.0f / (varM * 2.0f + 1e-6f);
        cF = sF[ty + 3][tx + 3];
        cM = sM[ty + 3][tx + 3];
    }

    int y = tileY + ty, x = tileX + tx;
    float eF[8], eM[8];
    float sumF = 0.f, sumM = 0.f;
    if (interior) {
        #pragma unroll
        for (int c = 0; c < 8; c++) {
            float oF = sF[ty + 3 + offdy[c]][tx + 3 + offdx[c]];
            float oM = sM[ty + 3 + offdy[c]][tx + 3 + offdx[c]];
            float dfF = cF - oF, dfM = cM - oM;
            float qF = fminf(dfF * dfF * invF, 50.0f);
            float qM = fminf(dfM * dfM * invM, 50.0f);
            eF[c] = __expf(-qF);
            eM[c] = __expf(-qM);
            sumF += eF[c];
            sumM += eM[c];
        }
    } else {
        #pragma unroll
        for (int c = 0; c < 8; c++) {
            int rr = clampi(y + offdy[c], 0, HP - 1) - gy0;
            int cc = clampi(x + offdx[c], 0, HP - 1) - gx0;
            float oF = sF[rr][cc], oM = sM[rr][cc];
            float dfF = cF - oF, dfM = cM - oM;
            float qF = fminf(dfF * dfF * invF, 50.0f);
            float qM = fminf(dfM * dfM * invM, 50.0f);
            eF[c] = __expf(-qF);
            eM[c] = __expf(-qM);
            sumF += eF[c];
            sumM += eM[c];
        }
    }
    float rF = 1.0f / (sumF + 1e-8f), rM = 1.0f / (sumM + 1e-8f);
    #pragma unroll
    for (int c = 0; c < 8; c++) {
        g_diff[b * 8 + c][y][x] = __float2half(eF[c] * rF - eM[c] * rM);
    }
}

// ------ bilinear upsample + |.| partials, hist collapse (blocks 0-7),
//        and last-block-done fused epilogue (replaces k_final) ------
#define UP_ROWS 32
__global__ __launch_bounds__(512) void k_up(float* __restrict__ out) {
    const float SCALE = 255.0f / 511.0f;
    __shared__ union {
        float xup[18][512];
        struct {
            float hp[8][256];
            float xh[8][16], yh[8][16];
            float nmi[8];
            float mind_p[8];
            float reg_p[4];
        } e;
    } sm;
    __shared__ float red[512];
    __shared__ unsigned int isLast;

    int t = threadIdx.x;

    // blocks 0-7: collapse hist strip partials (overwrite semantics)
    if (blockIdx.x < 8 && t < 256) {
        unsigned int c = 0;
        #pragma unroll
        for (int st = 0; st < 32; st++) c += g_hist_part[blockIdx.x][st][t];
        g_hist_agg[blockIdx.x][t] = c;
    }

    int plane = blockIdx.x >> 4;
    int strip = blockIdx.x & 15;
    int yo0 = strip * UP_ROWS;

    int rlo = clampi((int)floorf((float)yo0 * SCALE), 0, HP - 2);
    int rhi = clampi((int)floorf((float)(yo0 + UP_ROWS - 1) * SCALE), 0, HP - 2) + 1;
    int nrows = rhi - rlo + 1;

    float px = (float)t * SCALE;
    int j0 = clampi((int)floorf(px), 0, HP - 2);
    float fx = px - (float)j0;
    const __half* base = &g_diff[plane][0][0];
    for (int r = 0; r < nrows; r++) {
        const __half* row = base + (rlo + r) * HP;
        sm.xup[r][t] = __half2float(row[j0]) * (1.0f - fx) + __half2float(row[j0 + 1]) * fx;
    }
    __syncthreads();

    float acc = 0.f;
    #pragma unroll
    for (int l = 0; l < UP_ROWS; l++) {
        float pos = (float)(yo0 + l) * SCALE;
        int i0 = clampi((int)floorf(pos), 0, HP - 2);
        float fy = pos - (float)i0;
        float v0 = sm.xup[i0 - rlo][t];
        float v1 = sm.xup[i0 - rlo + 1][t];
        acc += fabsf(v0 * (1.0f - fy) + v1 * fy);
    }
    red[t] = acc;
    __syncthreads();
    #pragma unroll
    for (int s = 256; s > 0; s >>= 1) {
        if (t < s) red[t] += red[t + s];
        __syncthreads();
    }
    if (t == 0) g_part_mind[blockIdx.x] = red[0];

    // ---- last-block-done epilogue ----
    __threadfence();
    if (t == 0) isLast = (atomicAdd(&g_done, 1u) == (unsigned)(gridDim.x - 1)) ? 1u : 0u;
    __syncthreads();
    if (!isLast) return;

    int w = t >> 5;
    int lane = t & 31;

    if (w < 8) {
        // ---- batch w: MI/NMI entirely within this warp ----
        int b = w;
        uint4 u0 = __ldcg((const uint4*)&g_hist_agg[b][0] + lane * 2);
        uint4 u1 = __ldcg((const uint4*)&g_hist_agg[b][0] + lane * 2 + 1);
        float p[8];
        p[0] = (float)u0.x * (1.0f / 65536.0f); p[1] = (float)u0.y * (1.0f / 65536.0f);
        p[2] = (float)u0.z * (1.0f / 65536.0f); p[3] = (float)u0.w * (1.0f / 65536.0f);
        p[4] = (float)u1.x * (1.0f / 65536.0f); p[5] = (float)u1.y * (1.0f / 65536.0f);
        p[6] = (float)u1.z * (1.0f / 65536.0f); p[7] = (float)u1.w * (1.0f / 65536.0f);
        #pragma unroll
        for (int k = 0; k < 8; k++) sm.e.hp[b][lane * 8 + k] = p[k];
        __syncwarp();
        if (lane < 16) {
            float s = 0.f;
            #pragma unroll
            for (int j = 0; j < 16; j++) s += sm.e.hp[b][lane * 16 + j];
            sm.e.xh[b][lane] = s + 1e-5f;
        } else {
            int col = lane - 16;
            float s = 0.f;
            #pragma unroll
            for (int i = 0; i < 16; i++) s += sm.e.hp[b][i * 16 + col];
            sm.e.yh[b][col] = s + 1e-5f;
        }
        __syncwarp();
        int row = (lane * 8) >> 4;
        float xr = sm.e.xh[b][row];
        int cbase = (lane * 8) & 15;
        float term = 0.f;
        #pragma unroll
        for (int k = 0; k < 8; k++) {
            float hpe = p[k] + 1e-5f;
            term += hpe * (__logf(hpe) - __logf(xr * sm.e.yh[b][cbase + k]));
        }
        #pragma unroll
        for (int o = 16; o > 0; o >>= 1)
            term += __shfl_down_sync(0xffffffffu, term, o);
        if (lane == 0) {
            float mi = term;
            float hx = 0.f, hy = 0.f;
            #pragma unroll
            for (int k = 0; k < 16; k++) {
                hx -= sm.e.xh[b][k] * __logf(sm.e.xh[b][k]);
                hy -= sm.e.yh[b][k] * __logf(sm.e.yh[b][k]);
            }
            float se = hx + hy;
            float nmi = (se < 1e-10f) ? 0.0f : 2.0f * mi / se;
            sm.e.nmi[b] = fminf(fmaxf(nmi, -1.0f), 1.0f);
        }
    } else {
        // ---- mind partials: 1024 floats across warps 8-15 (float4/lane) ----
        int i = (w - 8) * 32 + lane;   // 0..255
        float4 v;
        v.x = __ldcg(&g_part_mind[4 * i]);
        v.y = __ldcg(&g_part_mind[4 * i + 1]);
        v.z = __ldcg(&g_part_mind[4 * i + 2]);
        v.w = __ldcg(&g_part_mind[4 * i + 3]);
        float s = (v.x + v.y) + (v.z + v.w);
        #pragma unroll
        for (int o = 16; o > 0; o >>= 1)
            s += __shfl_down_sync(0xffffffffu, s, o);
        if (lane == 0) sm.e.mind_p[w - 8] = s;

        // ---- reg partials: 512 floats across warps 8-11 (float4/lane) ----
        if (w < 12) {
            int j = (w - 8) * 32 + lane;   // 0..127
            float4 r4;
            r4.x = __ldcg(&g_part_reg[4 * j]);
            r4.y = __ldcg(&g_part_reg[4 * j + 1]);
            r4.z = __ldcg(&g_part_reg[4 * j + 2]);
            r4.w = __ldcg(&g_part_reg[4 * j + 3]);
            float sr = (r4.x + r4.y) + (r4.z + r4.w);
            #pragma unroll
            for (int o = 16; o > 0; o >>= 1)
                sr += __shfl_down_sync(0xffffffffu, sr, o);
            if (lane == 0) sm.e.reg_p[w - 8] = sr;
        }
    }
    __syncthreads();

    if (t == 0) {
        float mind = 0.f;
        #pragma unroll
        for (int k = 0; k < 8; k++) mind += sm.e.mind_p[k];
        float reg = (sm.e.reg_p[0] + sm.e.reg_p[1]) + (sm.e.reg_p[2] + sm.e.reg_p[3]);
        float accn = 0.f;
        #pragma unroll
        for (int b = 0; b < BATCH; b++) accn += sm.e.nmi[b];
        float m = fminf(fmaxf(accn * (1.0f / BATCH), -1.0f), 1.0f);
        out[0] = -m
               + 5.0f * (mind * (1.0f / 16777216.0f))
               + 0.1f * (reg * (1.0f / 524288.0f));
        g_done = 0u;   // reset for next graph replay
    }
}

// ---------------- launch ----------------
extern "C" void kernel_launch(void* const* d_in, const int* in_sizes, int n_in,
                              void* d_out, int out_size) {
    const float* fixed = (const float*)d_in[0];
    const float* moved = (const float*)d_in[1];
    const float* flow  = (const float*)d_in[2];
    if (n_in >= 3) {
        int fi = -1;
        for (int i = 0; i < 3; i++) if (in_sizes[i] == 2 * BATCH * HF * HF) fi = i;
        if (fi == 0) { flow = (const float*)d_in[0]; fixed = (const float*)d_in[1]; moved = (const float*)d_in[2]; }
        else if (fi == 1) { fixed = (const float*)d_in[0]; flow = (const float*)d_in[1]; moved = (const float*)d_in[2]; }
    }

    k_front<<<1024, 256>>>(fixed, moved, flow);
    k_mind<<<dim3(HP / BX, HP / BY, BATCH), dim3(BX, BY)>>>();
    k_up<<<1024, 512>>>((float*)d_out);
}

// round 8
// speedup vs baseline: 1.0894x; 1.0894x over previous
#include <cuda_runtime.h>
#include <cuda_fp16.h>
#include <math.h>

#define BATCH 8
#define HP 256        // pooled H/W
#define HF 512        // full H/W

// Scratch (device globals — no allocation allowed; zero-initialized at load)
__device__ __half g_diff[BATCH * 8][HP][HP];      // mind descriptor diff (8MB, fp16)
__device__ unsigned int g_hist_agg[BATCH][256];   // self-resetting each run
__device__ float g_part_mind[1024];
__device__ float g_part_reg[256];
__device__ unsigned int g_done;                   // self-resetting each run

__device__ __forceinline__ float san(float v) { return (v == v) ? v : 0.0f; }
__device__ __forceinline__ int clampi(int v, int lo, int hi) { return min(max(v, lo), hi); }

// =================== kernel 1: MIND (pool fused) + hist + flow regularizer ========
// grid 1280 x 512:
//   blocks [0,1024): MIND tiles (32x16 pooled px), pooling from full-res, + hist
//   blocks [1024,1280): regularizer strips (8 pooled rows), pooling from full-res
#define BX 32
#define BY 16
#define SW 38   // BX + 6

__global__ __launch_bounds__(512) void k_main(const float* __restrict__ fixed,
                                              const float* __restrict__ moved,
                                              const float* __restrict__ flow) {
    __shared__ union {
        struct {
            float sF[BY + 6][SW];
            float sM[BY + 6][SW];
            float hF[BY + 4][BX + 2];
            float hM[BY + 4][BX + 2];
            float vF[BY + 2][BX + 2];
            float vM[BY + 2][BX + 2];
            float hvF[BY + 2][BX];
            float hvM[BY + 2][BX];
            unsigned int sh[256];
        } m;
        struct {
            float su[10][256];
            float sv[10][256];
            float red[512];
        } r;
    } S;

    int blk = blockIdx.x;
    int tid = threadIdx.x;

    if (blk < 1024) {
        // ================= MIND tile =================
        int b = blk >> 7;
        int rem = blk & 127;
        int bxi = rem & 7;          // 0..7
        int byi = rem >> 3;         // 0..15
        int tileX = bxi * BX, tileY = byi * BY;
        int gx0 = tileX - 3, gy0 = tileY - 3;
        int tx = tid & 31, ty = tid >> 5;     // 32x16 layout
        const float* fF = fixed + (size_t)b * HF * HF;
        const float* fM = moved + (size_t)b * HF * HF;

        bool interior = (bxi >= 1) && (bxi <= 6) && (byi >= 1) && (byi <= 14);

        if (tid < 256) S.m.sh[tid] = 0u;

        // hist raw samples for owned pixel (full-res even coords)
        int oy = tileY + ty, ox = tileX + tx;
        float a_raw = san(__ldg(&fF[(size_t)(2 * oy) * HF + 2 * ox]));
        float m_raw = san(__ldg(&fM[(size_t)(2 * oy) * HF + 2 * ox]));

        // pooled tile + halo loader (clamped, from full-res)
        for (int s = tid; s < (BY + 6) * SW; s += 512) {
            int sy = s / SW, sx = s % SW;
            int gy = clampi(gy0 + sy, 0, HP - 1);
            int gx = clampi(gx0 + sx, 0, HP - 1);
            const float2* pF = (const float2*)(fF + (size_t)(2 * gy) * HF) + gx;
            float2 aF = pF[0], cF2 = pF[HF / 2];
            S.m.sF[sy][sx] = 0.25f * (san(aF.x) + san(aF.y) + san(cF2.x) + san(cF2.y));
            const float2* pM = (const float2*)(fM + (size_t)(2 * gy) * HF) + gx;
            float2 aM = pM[0], cM2 = pM[HF / 2];
            S.m.sM[sy][sx] = 0.25f * (san(aM.x) + san(aM.y) + san(cM2.x) + san(cM2.y));
        }
        __syncthreads();

        // hist atomics (sh zeroed before the sync above)
        {
            float xf = fminf(fmaxf((a_raw + 1.0f) * 0.5f, 0.001f), 0.999f);
            float yf = fminf(fmaxf((m_raw + 1.0f) * 0.5f, 0.001f), 0.999f);
            // searchsorted(linspace(0,1,17),v,'left')-1 == ceil(v*16)-1 on exact grid
            int xb = clampi((int)ceilf(xf * 16.0f) - 1, 0, 15);
            int yb = clampi((int)ceilf(yf * 16.0f) - 1, 0, 15);
            atomicAdd(&S.m.sh[xb * 16 + yb], 1u);
        }

        const int offdx[8] = {-2, -2, -2, 0, 0, 2, 2, 2};
        const int offdy[8] = {-2, 0, 2, -2, 2, -2, 0, 2};
        float cF, cM, invF, invM;

        if (interior) {
            // horizontal 3-sum (taps vc-2..vc)
            for (int s = tid; s < (BY + 4) * (BX + 2); s += 512) {
                int sy = s / (BX + 2), sx = s % (BX + 2);
                S.m.hF[sy][sx] = S.m.sF[sy][sx] + S.m.sF[sy][sx + 1] + S.m.sF[sy][sx + 2];
                S.m.hM[sy][sx] = S.m.sM[sy][sx] + S.m.sM[sy][sx + 1] + S.m.sM[sy][sx + 2];
            }
            __syncthreads();

            for (int s = tid; s < (BY + 2) * (BX + 2); s += 512) {
                int sy = s / (BX + 2), sx = s % (BX + 2);
                float pmF = S.m.hF[sy][sx] + S.m.hF[sy + 1][sx] + S.m.hF[sy + 2][sx];
                float pmM = S.m.hM[sy][sx] + S.m.hM[sy + 1][sx] + S.m.hM[sy + 2][sx];
                float dF = S.m.sF[sy + 2][sx + 2] - pmF * (1.0f / 9.0f);
                float dM = S.m.sM[sy + 2][sx + 2] - pmM * (1.0f / 9.0f);
                S.m.vF[sy][sx] = dF * dF;
                S.m.vM[sy][sx] = dM * dM;
            }
            __syncthreads();

            for (int s = tid; s < (BY + 2) * BX; s += 512) {
                int sy = s >> 5, sx = s & 31;
                S.m.hvF[sy][sx] = S.m.vF[sy][sx] + S.m.vF[sy][sx + 1] + S.m.vF[sy][sx + 2];
                S.m.hvM[sy][sx] = S.m.vM[sy][sx] + S.m.vM[sy][sx + 1] + S.m.vM[sy][sx + 2];
            }
            __syncthreads();

            float varF = fmaxf((S.m.hvF[ty][tx] + S.m.hvF[ty + 1][tx] + S.m.hvF[ty + 2][tx]) * (1.0f / 9.0f), 1e-4f);
            float varM = fmaxf((S.m.hvM[ty][tx] + S.m.hvM[ty + 1][tx] + S.m.hvM[ty + 2][tx]) * (1.0f / 9.0f), 1e-4f);
            invF = 1.0f / (varF * 2.0f + 1e-6f);
            invM = 1.0f / (varM * 2.0f + 1e-6f);
            cF = S.m.sF[ty + 3][tx + 3];
            cM = S.m.sM[ty + 3][tx + 3];
        } else {
            // border path: exact clamped semantics
            for (int s = tid; s < (BY + 2) * (BX + 2); s += 512) {
                int sy = s / (BX + 2), sx = s % (BX + 2);
                int uc = clampi(tileY - 1 + sy, 0, HP - 1);
                int vc = clampi(tileX - 1 + sx, 0, HP - 1);
                float pmF = 0.f, pmM = 0.f;
                #pragma unroll
                for (int a = 0; a < 3; a++) {
                    int rr = clampi(uc - 2 + a, 0, HP - 1) - gy0;
                    #pragma unroll
                    for (int bb = 0; bb < 3; bb++) {
                        int cc = clampi(vc - 2 + bb, 0, HP - 1) - gx0;
                        pmF += S.m.sF[rr][cc];
                        pmM += S.m.sM[rr][cc];
                    }
                }
                float dF = S.m.sF[uc - gy0][vc - gx0] - pmF * (1.0f / 9.0f);
                float dM = S.m.sM[uc - gy0][vc - gx0] - pmM * (1.0f / 9.0f);
                S.m.vF[sy][sx] = dF * dF;
                S.m.vM[sy][sx] = dM * dM;
            }
            __syncthreads();

            int y = tileY + ty, x = tileX + tx;
            float vsF = 0.f, vsM = 0.f;
            #pragma unroll
            for (int a = -1; a <= 1; a++) {
                int rr = clampi(y + a, 0, HP - 1) - (tileY - 1);
                #pragma unroll
                for (int bb = -1; bb <= 1; bb++) {
                    int cc = clampi(x + bb, 0, HP - 1) - (tileX - 1);
                    vsF += S.m.vF[rr][cc];
                    vsM += S.m.vM[rr][cc];
                }
            }
            float varF = fmaxf(vsF * (1.0f / 9.0f), 1e-4f);
            float varM = fmaxf(vsM * (1.0f / 9.0f), 1e-4f);
            invF = 1.0f / (varF * 2.0f + 1e-6f);
            invM = 1.0f / (varM * 2.0f + 1e-6f);
            cF = S.m.sF[ty + 3][tx + 3];
            cM = S.m.sM[ty + 3][tx + 3];
        }

        int y = tileY + ty, x = tileX + tx;
        float eF[8], eM[8];
        float sumF = 0.f, sumM = 0.f;
        if (interior) {
            #pragma unroll
            for (int c = 0; c < 8; c++) {
                float oF = S.m.sF[ty + 3 + offdy[c]][tx + 3 + offdx[c]];
                float oM = S.m.sM[ty + 3 + offdy[c]][tx + 3 + offdx[c]];
                float dfF = cF - oF, dfM = cM - oM;
                float qF = fminf(dfF * dfF * invF, 50.0f);
                float qM = fminf(dfM * dfM * invM, 50.0f);
                eF[c] = __expf(-qF);
                eM[c] = __expf(-qM);
                sumF += eF[c];
                sumM += eM[c];
            }
        } else {
            #pragma unroll
            for (int c = 0; c < 8; c++) {
                int rr = clampi(y + offdy[c], 0, HP - 1) - gy0;
                int cc = clampi(x + offdx[c], 0, HP - 1) - gx0;
                float oF = S.m.sF[rr][cc], oM = S.m.sM[rr][cc];
                float dfF = cF - oF, dfM = cM - oM;
                float qF = fminf(dfF * dfF * invF, 50.0f);
                float qM = fminf(dfM * dfM * invM, 50.0f);
                eF[c] = __expf(-qF);
                eM[c] = __expf(-qM);
                sumF += eF[c];
                sumM += eM[c];
            }
        }
        float rF = 1.0f / (sumF + 1e-8f), rM = 1.0f / (sumM + 1e-8f);
        #pragma unroll
        for (int c = 0; c < 8; c++) {
            g_diff[b * 8 + c][y][x] = __float2half(eF[c] * rF - eM[c] * rM);
        }

        // flush per-tile histogram (deterministic integer atomics)
        __syncthreads();
        if (tid < 256) {
            unsigned int cnt = S.m.sh[tid];
            if (cnt) atomicAdd(&g_hist_agg[b][tid], cnt);
        }
    } else {
        // ================= regularizer strip =================
        int q = blk - 1024;          // 0..255
        int b = q >> 5;
        int st = q & 31;             // 8 pooled rows per strip
        int sel = tid >> 8;          // 0 -> u, 1 -> v
        int tt = tid & 255;
        const float* base = flow + ((size_t)b * 2 + sel) * HF * HF;
        float (*sbuf)[256] = sel ? S.r.sv : S.r.su;

        #pragma unroll
        for (int r = 0; r < 10; r++) {
            int py = clampi(st * 8 - 1 + r, 0, HP - 1);
            const float2* p2 = (const float2*)(base + (size_t)(2 * py) * HF) + tt;
            float2 a = p2[0], c = p2[HF / 2];
            sbuf[r][tt] = 0.25f * (san(a.x) + san(a.y) + san(c.x) + san(c.y));
        }
        __syncthreads();

        int x = tid & 255;
        int rg = tid >> 8;           // 0,1 -> rows rg*4 .. rg*4+3
        int xm = max(x - 1, 0), xp = min(x + 1, HP - 1);
        float acc = 0.f;
        #pragma unroll
        for (int k = 0; k < 4; k++) {
            int r = rg * 4 + k + 1;
            float u00 = S.r.su[r - 1][xm], u01 = S.r.su[r - 1][x], u02 = S.r.su[r - 1][xp];
            float u10 = S.r.su[r][xm],     u11 = S.r.su[r][x],     u12 = S.r.su[r][xp];
            float u20 = S.r.su[r + 1][xm], u21 = S.r.su[r + 1][x], u22 = S.r.su[r + 1][xp];
            float v00 = S.r.sv[r - 1][xm], v01 = S.r.sv[r - 1][x], v02 = S.r.sv[r - 1][xp];
            float v10 = S.r.sv[r][xm],     v11 = S.r.sv[r][x],     v12 = S.r.sv[r][xp];
            float v20 = S.r.sv[r + 1][xm], v21 = S.r.sv[r + 1][x], v22 = S.r.sv[r + 1][xp];

            float gxu = (u02 + 2.f * u12 + u22) - (u00 + 2.f * u10 + u20);
            float gyu = (u20 + 2.f * u21 + u22) - (u00 + 2.f * u01 + u02);
            float lpu = u01 + u10 + u12 + u21 - 4.f * u11;
            float gxv = (v02 + 2.f * v12 + v22) - (v00 + 2.f * v10 + v20);
            float gyv = (v20 + 2.f * v21 + v22) - (v00 + 2.f * v01 + v02);
            float lpv = v01 + v10 + v12 + v21 - 4.f * v11;

            float gm = gxu * gxu + gyu * gyu + gxv * gxv + gyv * gyv;
            float lm = lpu * lpu + lpv * lpv;
            acc += fminf(gm, 100.0f) + fminf(lm, 100.0f);
        }
        __syncthreads();   // done reading su/sv before red overlays nothing (red separate)

        S.r.red[tid] = acc;
        __syncthreads();
        #pragma unroll
        for (int s = 256; s > 0; s >>= 1) {
            if (tid < s) S.r.red[tid] += S.r.red[tid + s];
            __syncthreads();
        }
        if (tid == 0) g_part_reg[q] = S.r.red[0];
    }
}

// ------ kernel 2: bilinear upsample + |.| partials + last-block fused epilogue ------
#define UP_ROWS 32
__global__ __launch_bounds__(512) void k_up(float* __restrict__ out) {
    const float SCALE = 255.0f / 511.0f;
    __shared__ union {
        float xup[18][512];
        struct {
            float hp[8][256];
            float xh[8][16], yh[8][16];
            float nmi[8];
            float mind_p[8];
            float reg_p[2];
        } e;
    } sm;
    __shared__ float red[512];
    __shared__ unsigned int isLast;

    int t = threadIdx.x;
    int plane = blockIdx.x >> 4;
    int strip = blockIdx.x & 15;
    int yo0 = strip * UP_ROWS;

    int rlo = clampi((int)floorf((float)yo0 * SCALE), 0, HP - 2);
    int rhi = clampi((int)floorf((float)(yo0 + UP_ROWS - 1) * SCALE), 0, HP - 2) + 1;
    int nrows = rhi - rlo + 1;

    float px = (float)t * SCALE;
    int j0 = clampi((int)floorf(px), 0, HP - 2);
    float fx = px - (float)j0;
    const __half* base = &g_diff[plane][0][0];
    for (int r = 0; r < nrows; r++) {
        const __half* row = base + (rlo + r) * HP;
        sm.xup[r][t] = __half2float(row[j0]) * (1.0f - fx) + __half2float(row[j0 + 1]) * fx;
    }
    __syncthreads();

    float acc = 0.f;
    #pragma unroll
    for (int l = 0; l < UP_ROWS; l++) {
        float pos = (float)(yo0 + l) * SCALE;
        int i0 = clampi((int)floorf(pos), 0, HP - 2);
        float fy = pos - (float)i0;
        float v0 = sm.xup[i0 - rlo][t];
        float v1 = sm.xup[i0 - rlo + 1][t];
        acc += fabsf(v0 * (1.0f - fy) + v1 * fy);
    }
    red[t] = acc;
    __syncthreads();
    #pragma unroll
    for (int s = 256; s > 0; s >>= 1) {
        if (t < s) red[t] += red[t + s];
        __syncthreads();
    }
    if (t == 0) g_part_mind[blockIdx.x] = red[0];

    // ---- last-block-done epilogue ----
    __threadfence();
    if (t == 0) isLast = (atomicAdd(&g_done, 1u) == (unsigned)(gridDim.x - 1)) ? 1u : 0u;
    __syncthreads();
    if (!isLast) return;

    int w = t >> 5;
    int lane = t & 31;

    if (w < 8) {
        // ---- batch w: MI/NMI entirely within this warp; self-reset hist after read ----
        int b = w;
        uint4 u0 = __ldcg((const uint4*)&g_hist_agg[b][0] + lane * 2);
        uint4 u1 = __ldcg((const uint4*)&g_hist_agg[b][0] + lane * 2 + 1);
        ((uint4*)&g_hist_agg[b][0])[lane * 2] = make_uint4(0, 0, 0, 0);
        ((uint4*)&g_hist_agg[b][0])[lane * 2 + 1] = make_uint4(0, 0, 0, 0);
        float p[8];
        p[0] = (float)u0.x * (1.0f / 65536.0f); p[1] = (float)u0.y * (1.0f / 65536.0f);
        p[2] = (float)u0.z * (1.0f / 65536.0f); p[3] = (float)u0.w * (1.0f / 65536.0f);
        p[4] = (float)u1.x * (1.0f / 65536.0f); p[5] = (float)u1.y * (1.0f / 65536.0f);
        p[6] = (float)u1.z * (1.0f / 65536.0f); p[7] = (float)u1.w * (1.0f / 65536.0f);
        #pragma unroll
        for (int k = 0; k < 8; k++) sm.e.hp[b][lane * 8 + k] = p[k];
        __syncwarp();
        if (lane < 16) {
            float s = 0.f;
            #pragma unroll
            for (int j = 0; j < 16; j++) s += sm.e.hp[b][lane * 16 + j];
            sm.e.xh[b][lane] = s + 1e-5f;
        } else {
            int col = lane - 16;
            float s = 0.f;
            #pragma unroll
            for (int i = 0; i < 16; i++) s += sm.e.hp[b][i * 16 + col];
            sm.e.yh[b][col] = s + 1e-5f;
        }
        __syncwarp();
        int row = (lane * 8) >> 4;
        float xr = sm.e.xh[b][row];
        int cbase = (lane * 8) & 15;
        float term = 0.f;
        #pragma unroll
        for (int k = 0; k < 8; k++) {
            float hpe = p[k] + 1e-5f;
            term += hpe * (__logf(hpe) - __logf(xr * sm.e.yh[b][cbase + k]));
        }
        #pragma unroll
        for (int o = 16; o > 0; o >>= 1)
            term += __shfl_down_sync(0xffffffffu, term, o);
        if (lane == 0) {
            float mi = term;
            float hx = 0.f, hy = 0.f;
            #pragma unroll
            for (int k = 0; k < 16; k++) {
                hx -= sm.e.xh[b][k] * __logf(sm.e.xh[b][k]);
                hy -= sm.e.yh[b][k] * __logf(sm.e.yh[b][k]);
            }
            float se = hx + hy;
            float nmi = (se < 1e-10f) ? 0.0f : 2.0f * mi / se;
            sm.e.nmi[b] = fminf(fmaxf(nmi, -1.0f), 1.0f);
        }
    } else {
        // ---- mind partials: 1024 floats across warps 8-15 (float4/lane) ----
        int i = (w - 8) * 32 + lane;   // 0..255
        float4 v;
        v.x = __ldcg(&g_part_mind[4 * i]);
        v.y = __ldcg(&g_part_mind[4 * i + 1]);
        v.z = __ldcg(&g_part_mind[4 * i + 2]);
        v.w = __ldcg(&g_part_mind[4 * i + 3]);
        float s = (v.x + v.y) + (v.z + v.w);
        #pragma unroll
        for (int o = 16; o > 0; o >>= 1)
            s += __shfl_down_sync(0xffffffffu, s, o);
        if (lane == 0) sm.e.mind_p[w - 8] = s;

        // ---- reg partials: 256 floats across warps 8-9 (float4/lane) ----
        if (w < 10) {
            int j = (w - 8) * 32 + lane;   // 0..63
            float4 r4;
            r4.x = __ldcg(&g_part_reg[4 * j]);
            r4.y = __ldcg(&g_part_reg[4 * j + 1]);
            r4.z = __ldcg(&g_part_reg[4 * j + 2]);
            r4.w = __ldcg(&g_part_reg[4 * j + 3]);
            float sr = (r4.x + r4.y) + (r4.z + r4.w);
            #pragma unroll
            for (int o = 16; o > 0; o >>= 1)
                sr += __shfl_down_sync(0xffffffffu, sr, o);
            if (lane == 0) sm.e.reg_p[w - 8] = sr;
        }
    }
    __syncthreads();

    if (t == 0) {
        float mind = 0.f;
        #pragma unroll
        for (int k = 0; k < 8; k++) mind += sm.e.mind_p[k];
        float reg = sm.e.reg_p[0] + sm.e.reg_p[1];
        float accn = 0.f;
        #pragma unroll
        for (int b = 0; b < BATCH; b++) accn += sm.e.nmi[b];
        float m = fminf(fmaxf(accn * (1.0f / BATCH), -1.0f), 1.0f);
        out[0] = -m
               + 5.0f * (mind * (1.0f / 16777216.0f))
               + 0.1f * (reg * (1.0f / 524288.0f));
        g_done = 0u;   // reset for next graph replay
    }
}

// ---------------- launch ----------------
extern "C" void kernel_launch(void* const* d_in, const int* in_sizes, int n_in,
                              void* d_out, int out_size) {
    const float* fixed = (const float*)d_in[0];
    const float* moved = (const float*)d_in[1];
    const float* flow  = (const float*)d_in[2];
    if (n_in >= 3) {
        int fi = -1;
        for (int i = 0; i < 3; i++) if (in_sizes[i] == 2 * BATCH * HF * HF) fi = i;
        if (fi == 0) { flow = (const float*)d_in[0]; fixed = (const float*)d_in[1]; moved = (const float*)d_in[2]; }
        else if (fi == 1) { fixed = (const float*)d_in[0]; flow = (const float*)d_in[1]; moved = (const float*)d_in[2]; }
    }

    k_main<<<1280, 512>>>(fixed, moved, flow);
    k_up<<<1024, 512>>>((float*)d_out);
}

// round 9
// speedup vs baseline: 1.3008x; 1.1941x over previous
#include <cuda_runtime.h>
#include <cuda_fp16.h>
#include <math.h>

#define BATCH 8
#define HP 256        // pooled H/W
#define HF 512        // full H/W
#define BX 32
#define BY 16
#define PR 23         // pooled rows loaded  (tileY-4 .. tileY+18)
#define PC 39         // pooled cols loaded  (tileX-4 .. tileX+34)
#define PCW 40        // pooled col stride
#define DR 18         // diff rows (tileY-1 .. tileY+16)
#define DC 34         // diff cols (tileX-1 .. tileX+32)
#define DPW 36        // dp col stride

// Scratch (device globals — zero-initialized; self-resetting each run)
__device__ unsigned int g_hist_agg[BATCH][256];
__device__ float g_part_mind[1024];
__device__ float g_part_reg[256];
__device__ unsigned int g_done;

__device__ __forceinline__ float san(float v) { return (v == v) ? v : 0.0f; }
__device__ __forceinline__ int clampi(int v, int lo, int hi) { return min(max(v, lo), hi); }

// ============ single fused kernel ============
// blocks [0,1024): MIND tiles: pool+hist+descriptors+diff+upsample+partial sum
// blocks [1024,1280): flow regularizer strips
__global__ __launch_bounds__(512) void k_main(const float* __restrict__ fixed,
                                              const float* __restrict__ moved,
                                              const float* __restrict__ flow,
                                              float* __restrict__ out) {
    __shared__ union {
        struct {
            float sF[PR][PCW], sM[PR][PCW];       // pooled + 4-halo
            float hF[22][36], hM[22][36];         // horiz 3-sums (patch mean)
            float vF[20][36], vM[20][36];         // variance_pre
            float hvF[20][34], hvM[20][34];       // horiz 3-sums of v
            float invF[DR][DC], invM[DR][DC];     // 1/(2var+1e-6)
            __half2 dp[4][DR][DPW];               // diff, 2 channels per half2
            float2 ytab[32];
            unsigned int sh[256];
            float red[16];
        } m;
        struct { float su[10][256], sv[10][256]; float red[512]; } r;
        struct { float hp[8][256]; float xh[8][16], yh[8][16];
                 float nmi[8]; float mind_p[8]; float reg_p[2]; } e;
    } S;

    const float SCALE = 255.0f / 511.0f;
    int blk = blockIdx.x;
    int tid = threadIdx.x;

    if (blk < 1024) {
        // ================= MIND tile =================
        int b = blk >> 7;
        int rem = blk & 127;
        int bxi = rem & 7, byi = rem >> 3;
        int tileX = bxi * BX, tileY = byi * BY;
        int gx0 = tileX - 4, gy0 = tileY - 4;
        const float* fF = fixed + (size_t)b * HF * HF;
        const float* fM = moved + (size_t)b * HF * HF;
        bool interior = (bxi >= 1) && (bxi <= 6) && (byi >= 1) && (byi <= 14);

        if (tid < 256) S.m.sh[tid] = 0u;

        // hist raw samples for owned tile pixel (full-res even coords)
        int ty = tid >> 5, tx = tid & 31;
        float a_raw = san(__ldg(&fF[(size_t)(2 * (tileY + ty)) * HF + 2 * (tileX + tx)]));
        float m_raw = san(__ldg(&fM[(size_t)(2 * (tileY + ty)) * HF + 2 * (tileX + tx)]));

        // y upsample table for this tile's 32 output rows
        if (tid < 32) {
            float pos = (float)(2 * tileY + tid) * SCALE;
            int i0 = clampi((int)floorf(pos), 0, HP - 2);
            S.m.ytab[tid] = make_float2(pos - (float)i0, __int_as_float(i0 - (tileY - 1)));
        }

        // pooled loader (from full-res), 4-halo
        if (interior) {
            for (int s = tid; s < PR * PC; s += 512) {
                int sy = s / PC, sx = s % PC;
                int gy = gy0 + sy, gx = gx0 + sx;
                const float2* pF = (const float2*)(fF + (size_t)(2 * gy) * HF) + gx;
                float2 aF = pF[0], cF2 = pF[HF / 2];
                S.m.sF[sy][sx] = 0.25f * (san(aF.x) + san(aF.y) + san(cF2.x) + san(cF2.y));
                const float2* pM = (const float2*)(fM + (size_t)(2 * gy) * HF) + gx;
                float2 aM = pM[0], cM2 = pM[HF / 2];
                S.m.sM[sy][sx] = 0.25f * (san(aM.x) + san(aM.y) + san(cM2.x) + san(cM2.y));
            }
        } else {
            for (int s = tid; s < PR * PC; s += 512) {
                int sy = s / PC, sx = s % PC;
                int gy = clampi(gy0 + sy, 0, HP - 1), gx = clampi(gx0 + sx, 0, HP - 1);
                const float2* pF = (const float2*)(fF + (size_t)(2 * gy) * HF) + gx;
                float2 aF = pF[0], cF2 = pF[HF / 2];
                S.m.sF[sy][sx] = 0.25f * (san(aF.x) + san(aF.y) + san(cF2.x) + san(cF2.y));
                const float2* pM = (const float2*)(fM + (size_t)(2 * gy) * HF) + gx;
                float2 aM = pM[0], cM2 = pM[HF / 2];
                S.m.sM[sy][sx] = 0.25f * (san(aM.x) + san(aM.y) + san(cM2.x) + san(cM2.y));
            }
        }
        __syncthreads();

        // histogram (shared atomics; searchsorted-left == ceil(v*16)-1 on exact grid)
        {
            float xf = fminf(fmaxf((a_raw + 1.0f) * 0.5f, 0.001f), 0.999f);
            float yf = fminf(fmaxf((m_raw + 1.0f) * 0.5f, 0.001f), 0.999f);
            int xb = clampi((int)ceilf(xf * 16.0f) - 1, 0, 15);
            int yb = clampi((int)ceilf(yf * 16.0f) - 1, 0, 15);
            atomicAdd(&S.m.sh[xb * 16 + yb], 1u);
        }

        if (interior) {
            // h: horizontal 3-sum (patch-mean taps vc-2..vc)
            for (int s = tid; s < 22 * 36; s += 512) {
                int u = s / 36, j = s % 36;
                S.m.hF[u][j] = S.m.sF[u][j] + S.m.sF[u][j + 1] + S.m.sF[u][j + 2];
                S.m.hM[u][j] = S.m.sM[u][j] + S.m.sM[u][j + 1] + S.m.sM[u][j + 2];
            }
            __syncthreads();
            // variance_pre at global (tileY-2+iy, tileX-2+jx)
            for (int s = tid; s < 20 * 36; s += 512) {
                int iy = s / 36, jx = s % 36;
                float pmF = S.m.hF[iy][jx] + S.m.hF[iy + 1][jx] + S.m.hF[iy + 2][jx];
                float pmM = S.m.hM[iy][jx] + S.m.hM[iy + 1][jx] + S.m.hM[iy + 2][jx];
                float dF = S.m.sF[iy + 2][jx + 2] - pmF * (1.0f / 9.0f);
                float dM = S.m.sM[iy + 2][jx + 2] - pmM * (1.0f / 9.0f);
                S.m.vF[iy][jx] = dF * dF;
                S.m.vM[iy][jx] = dM * dM;
            }
            __syncthreads();
            // hv: horizontal 3-sum of v
            for (int s = tid; s < 20 * 34; s += 512) {
                int iy = s / 34, mc = s % 34;
                S.m.hvF[iy][mc] = S.m.vF[iy][mc] + S.m.vF[iy][mc + 1] + S.m.vF[iy][mc + 2];
                S.m.hvM[iy][mc] = S.m.vM[iy][mc] + S.m.vM[iy][mc + 1] + S.m.vM[iy][mc + 2];
            }
            __syncthreads();
            // inv at diff positions
            for (int s = tid; s < DR * DC; s += 512) {
                int a = s / DC, b2 = s % DC;
                float varF = fmaxf((S.m.hvF[a][b2] + S.m.hvF[a + 1][b2] + S.m.hvF[a + 2][b2]) * (1.0f / 9.0f), 1e-4f);
                float varM = fmaxf((S.m.hvM[a][b2] + S.m.hvM[a + 1][b2] + S.m.hvM[a + 2][b2]) * (1.0f / 9.0f), 1e-4f);
                S.m.invF[a][b2] = 1.0f / (varF * 2.0f + 1e-6f);
                S.m.invM[a][b2] = 1.0f / (varM * 2.0f + 1e-6f);
            }
            __syncthreads();
        } else {
            // border: variance_pre with clamped taps
            for (int s = tid; s < 20 * 36; s += 512) {
                int iy = s / 36, jx = s % 36;
                int gv = tileY - 2 + iy, gc = tileX - 2 + jx;
                float pmF = 0.f, pmM = 0.f;
                #pragma unroll
                for (int aa = 0; aa < 3; aa++) {
                    int rr = clampi(gv - 2 + aa, 0, HP - 1) - gy0;
                    #pragma unroll
                    for (int bb = 0; bb < 3; bb++) {
                        int cc = clampi(gc - 2 + bb, 0, HP - 1) - gx0;
                        pmF += S.m.sF[rr][cc];
                        pmM += S.m.sM[rr][cc];
                    }
                }
                float dF = S.m.sF[iy + 2][jx + 2] - pmF * (1.0f / 9.0f);
                float dM = S.m.sM[iy + 2][jx + 2] - pmM * (1.0f / 9.0f);
                S.m.vF[iy][jx] = dF * dF;
                S.m.vM[iy][jx] = dM * dM;
            }
            __syncthreads();
            // border: var (replicate-pad conv) + inv
            for (int s = tid; s < DR * DC; s += 512) {
                int a = s / DC, b2 = s % DC;
                int gdy = tileY - 1 + a, gdx = tileX - 1 + b2;
                float vsF = 0.f, vsM = 0.f;
                #pragma unroll
                for (int dy2 = -1; dy2 <= 1; dy2++) {
                    int iy = clampi(gdy + dy2, 0, HP - 1) - (tileY - 2);
                    #pragma unroll
                    for (int dx2 = -1; dx2 <= 1; dx2++) {
                        int jx = clampi(gdx + dx2, 0, HP - 1) - (tileX - 2);
                        vsF += S.m.vF[iy][jx];
                        vsM += S.m.vM[iy][jx];
                    }
                }
                float varF = fmaxf(vsF * (1.0f / 9.0f), 1e-4f);
                float varM = fmaxf(vsM * (1.0f / 9.0f), 1e-4f);
                S.m.invF[a][b2] = 1.0f / (varF * 2.0f + 1e-6f);
                S.m.invM[a][b2] = 1.0f / (varM * 2.0f + 1e-6f);
            }
            __syncthreads();
        }

        // diff channels on DRxDC region (includes 1-halo for upsample)
        {
            const int offdx[8] = {-2, -2, -2, 0, 0, 2, 2, 2};
            const int offdy[8] = {-2, 0, 2, -2, 2, -2, 0, 2};
            for (int s = tid; s < DR * DC; s += 512) {
                int a = s / DC, b2 = s % DC;
                float cF = S.m.sF[a + 3][b2 + 3], cM = S.m.sM[a + 3][b2 + 3];
                float iF = S.m.invF[a][b2], iM = S.m.invM[a][b2];
                float eF[8], eM[8];
                float sumF = 0.f, sumM = 0.f;
                if (interior) {
                    #pragma unroll
                    for (int c = 0; c < 8; c++) {
                        float oF = S.m.sF[a + 3 + offdy[c]][b2 + 3 + offdx[c]];
                        float oM = S.m.sM[a + 3 + offdy[c]][b2 + 3 + offdx[c]];
                        float dfF = cF - oF, dfM = cM - oM;
                        float qF = fminf(dfF * dfF * iF, 50.0f);
                        float qM = fminf(dfM * dfM * iM, 50.0f);
                        eF[c] = __expf(-qF); eM[c] = __expf(-qM);
                        sumF += eF[c]; sumM += eM[c];
                    }
                } else {
                    #pragma unroll
                    for (int c = 0; c < 8; c++) {
                        int rr = clampi(tileY - 1 + a + offdy[c], 0, HP - 1) - gy0;
                        int cc = clampi(tileX - 1 + b2 + offdx[c], 0, HP - 1) - gx0;
                        float oF = S.m.sF[rr][cc], oM = S.m.sM[rr][cc];
                        float dfF = cF - oF, dfM = cM - oM;
                        float qF = fminf(dfF * dfF * iF, 50.0f);
                        float qM = fminf(dfM * dfM * iM, 50.0f);
                        eF[c] = __expf(-qF); eM[c] = __expf(-qM);
                        sumF += eF[c]; sumM += eM[c];
                    }
                }
                float rF = 1.0f / (sumF + 1e-8f), rM = 1.0f / (sumM + 1e-8f);
                #pragma unroll
                for (int p = 0; p < 4; p++) {
                    float d0 = eF[2 * p] * rF - eM[2 * p] * rM;
                    float d1 = eF[2 * p + 1] * rF - eM[2 * p + 1] * rM;
                    S.m.dp[p][a][b2] = __floats2half2_rn(d0, d1);
                }
            }
        }
        __syncthreads();

        // ---- in-tile bilinear upsample (align corners) + |.| accumulate ----
        // thread -> output col lx = tid&63 (X = 2*tileX+lx), rows ly = 4*(tid>>6)+k
        float acc = 0.f;
        {
            int lx = tid & 63;
            int qy = tid >> 6;
            float posx = (float)(2 * tileX + lx) * SCALE;
            int j0 = clampi((int)floorf(posx), 0, HP - 2);
            float fx = posx - (float)j0;
            int rx = j0 - (tileX - 1);       // 0..32
            __half2 wx0 = __float2half2_rn(1.0f - fx), wx1 = __float2half2_rn(fx);

            float2 yt[4];
            #pragma unroll
            for (int k = 0; k < 4; k++) yt[k] = S.m.ytab[qy * 4 + k];
            int rbase = __float_as_int(yt[0].y);

            __half2 xv[4][4];
            #pragma unroll
            for (int rr = 0; rr < 4; rr++) {
                int row = min(rbase + rr, DR - 1);
                #pragma unroll
                for (int p = 0; p < 4; p++) {
                    __half2 t0 = S.m.dp[p][row][rx];
                    __half2 t1 = S.m.dp[p][row][rx + 1];
                    xv[p][rr] = __hfma2(t1, wx1, __hmul2(t0, wx0));
                }
            }
            #pragma unroll
            for (int k = 0; k < 4; k++) {
                float fy = yt[k].x;
                int ri = __float_as_int(yt[k].y) - rbase;   // 0..2
                __half2 wy0 = __float2half2_rn(1.0f - fy), wy1 = __float2half2_rn(fy);
                #pragma unroll
                for (int p = 0; p < 4; p++) {
                    __half2 val = __hfma2(xv[p][ri + 1], wy1, __hmul2(xv[p][ri], wy0));
                    float2 vf = __half22float2(val);
                    acc += fabsf(vf.x) + fabsf(vf.y);
                }
            }
        }
        // block reduce (deterministic)
        #pragma unroll
        for (int o = 16; o > 0; o >>= 1)
            acc += __shfl_down_sync(0xffffffffu, acc, o);
        if ((tid & 31) == 0) S.m.red[tid >> 5] = acc;
        __syncthreads();
        if (tid == 0) {
            float s = 0.f;
            #pragma unroll
            for (int k = 0; k < 16; k++) s += S.m.red[k];
            g_part_mind[blk] = s;
        }
        // flush per-tile histogram
        if (tid < 256) {
            unsigned int cnt = S.m.sh[tid];
            if (cnt) atomicAdd(&g_hist_agg[b][tid], cnt);
        }
    } else {
        // ================= regularizer strip =================
        int q = blk - 1024;          // 0..255
        int b = q >> 5;
        int st = q & 31;             // 8 pooled rows per strip
        int sel = tid >> 8;          // 0 -> u, 1 -> v
        int tt = tid & 255;
        const float* base = flow + ((size_t)b * 2 + sel) * HF * HF;
        float (*sbuf)[256] = sel ? S.r.sv : S.r.su;

        #pragma unroll
        for (int rr = 0; rr < 10; rr++) {
            int py = clampi(st * 8 - 1 + rr, 0, HP - 1);
            const float2* p2 = (const float2*)(base + (size_t)(2 * py) * HF) + tt;
            float2 a = p2[0], c = p2[HF / 2];
            sbuf[rr][tt] = 0.25f * (san(a.x) + san(a.y) + san(c.x) + san(c.y));
        }
        __syncthreads();

        int x = tid & 255;
        int rg = tid >> 8;
        int xm = max(x - 1, 0), xp = min(x + 1, HP - 1);
        float acc = 0.f;
        #pragma unroll
        for (int k = 0; k < 4; k++) {
            int rr = rg * 4 + k + 1;
            float u00 = S.r.su[rr - 1][xm], u01 = S.r.su[rr - 1][x], u02 = S.r.su[rr - 1][xp];
            float u10 = S.r.su[rr][xm],     u11 = S.r.su[rr][x],     u12 = S.r.su[rr][xp];
            float u20 = S.r.su[rr + 1][xm], u21 = S.r.su[rr + 1][x], u22 = S.r.su[rr + 1][xp];
            float v00 = S.r.sv[rr - 1][xm], v01 = S.r.sv[rr - 1][x], v02 = S.r.sv[rr - 1][xp];
            float v10 = S.r.sv[rr][xm],     v11 = S.r.sv[rr][x],     v12 = S.r.sv[rr][xp];
            float v20 = S.r.sv[rr + 1][xm], v21 = S.r.sv[rr + 1][x], v22 = S.r.sv[rr + 1][xp];

            float gxu = (u02 + 2.f * u12 + u22) - (u00 + 2.f * u10 + u20);
            float gyu = (u20 + 2.f * u21 + u22) - (u00 + 2.f * u01 + u02);
            float lpu = u01 + u10 + u12 + u21 - 4.f * u11;
            float gxv = (v02 + 2.f * v12 + v22) - (v00 + 2.f * v10 + v20);
            float gyv = (v20 + 2.f * v21 + v22) - (v00 + 2.f * v01 + v02);
            float lpv = v01 + v10 + v12 + v21 - 4.f * v11;

            float gm = gxu * gxu + gyu * gyu + gxv * gxv + gyv * gyv;
            float lm = lpu * lpu + lpv * lpv;
            acc += fminf(gm, 100.0f) + fminf(lm, 100.0f);
        }
        __syncthreads();
        S.r.red[tid] = acc;
        __syncthreads();
        #pragma unroll
        for (int s = 256; s > 0; s >>= 1) {
            if (tid < s) S.r.red[tid] += S.r.red[tid + s];
            __syncthreads();
        }
        if (tid == 0) g_part_reg[q] = S.r.red[0];
    }

    // ================= last-block-done fused epilogue =================
    __threadfence();
    __syncthreads();
    __shared__ unsigned int isLast;
    if (tid == 0) isLast = (atomicAdd(&g_done, 1u) == (unsigned)(gridDim.x - 1)) ? 1u : 0u;
    __syncthreads();
    if (!isLast) return;

    int w = tid >> 5;
    int lane = tid & 31;

    if (w < 8) {
        int b = w;
        uint4 u0 = __ldcg((const uint4*)&g_hist_agg[b][0] + lane * 2);
        uint4 u1 = __ldcg((const uint4*)&g_hist_agg[b][0] + lane * 2 + 1);
        ((uint4*)&g_hist_agg[b][0])[lane * 2] = make_uint4(0, 0, 0, 0);
        ((uint4*)&g_hist_agg[b][0])[lane * 2 + 1] = make_uint4(0, 0, 0, 0);
        float p[8];
        p[0] = (float)u0.x * (1.0f / 65536.0f); p[1] = (float)u0.y * (1.0f / 65536.0f);
        p[2] = (float)u0.z * (1.0f / 65536.0f); p[3] = (float)u0.w * (1.0f / 65536.0f);
        p[4] = (float)u1.x * (1.0f / 65536.0f); p[5] = (float)u1.y * (1.0f / 65536.0f);
        p[6] = (float)u1.z * (1.0f / 65536.0f); p[7] = (float)u1.w * (1.0f / 65536.0f);
        #pragma unroll
        for (int k = 0; k < 8; k++) S.e.hp[b][lane * 8 + k] = p[k];
        __syncwarp();
        if (lane < 16) {
            float s = 0.f;
            #pragma unroll
            for (int j = 0; j < 16; j++) s += S.e.hp[b][lane * 16 + j];
            S.e.xh[b][lane] = s + 1e-5f;
        } else {
            int col = lane - 16;
            float s = 0.f;
            #pragma unroll
            for (int i = 0; i < 16; i++) s += S.e.hp[b][i * 16 + col];
            S.e.yh[b][col] = s + 1e-5f;
        }
        __syncwarp();
        int row = (lane * 8) >> 4;
        float xr = S.e.xh[b][row];
        int cbase = (lane * 8) & 15;
        float term = 0.f;
        #pragma unroll
        for (int k = 0; k < 8; k++) {
            float hpe = p[k] + 1e-5f;
            term += hpe * (__logf(hpe) - __logf(xr * S.e.yh[b][cbase + k]));
        }
        #pragma unroll
        for (int o = 16; o > 0; o >>= 1)
            term += __shfl_down_sync(0xffffffffu, term, o);
        if (lane == 0) {
            float mi = term;
            float hx = 0.f, hy = 0.f;
            #pragma unroll
            for (int k = 0; k < 16; k++) {
                hx -= S.e.xh[b][k] * __logf(S.e.xh[b][k]);
                hy -= S.e.yh[b][k] * __logf(S.e.yh[b][k]);
            }
            float se = hx + hy;
            float nmi = (se < 1e-10f) ? 0.0f : 2.0f * mi / se;
            S.e.nmi[b] = fminf(fmaxf(nmi, -1.0f), 1.0f);
        }
    } else {
        // mind partials: 1024 floats across warps 8-15 (float4/lane)
        int i = (w - 8) * 32 + lane;   // 0..255
        float4 v;
        v.x = __ldcg(&g_part_mind[4 * i]);
        v.y = __ldcg(&g_part_mind[4 * i + 1]);
        v.z = __ldcg(&g_part_mind[4 * i + 2]);
        v.w = __ldcg(&g_part_mind[4 * i + 3]);
        float s = (v.x + v.y) + (v.z + v.w);
        #pragma unroll
        for (int o = 16; o > 0; o >>= 1)
            s += __shfl_down_sync(0xffffffffu, s, o);
        if (lane == 0) S.e.mind_p[w - 8] = s;

        // reg partials: 256 floats across warps 8-9 (float4/lane)
        if (w < 10) {
            int j = (w - 8) * 32 + lane;   // 0..63
            float4 r4;
            r4.x = __ldcg(&g_part_reg[4 * j]);
            r4.y = __ldcg(&g_part_reg[4 * j + 1]);
            r4.z = __ldcg(&g_part_reg[4 * j + 2]);
            r4.w = __ldcg(&g_part_reg[4 * j + 3]);
            float sr = (r4.x + r4.y) + (r4.z + r4.w);
            #pragma unroll
            for (int o = 16; o > 0; o >>= 1)
                sr += __shfl_down_sync(0xffffffffu, sr, o);
            if (lane == 0) S.e.reg_p[w - 8] = sr;
        }
    }
    __syncthreads();

    if (tid == 0) {
        float mind = 0.f;
        #pragma unroll
        for (int k = 0; k < 8; k++) mind += S.e.mind_p[k];
        float reg = S.e.reg_p[0] + S.e.reg_p[1];
        float accn = 0.f;
        #pragma unroll
        for (int b = 0; b < BATCH; b++) accn += S.e.nmi[b];
        float mm = fminf(fmaxf(accn * (1.0f / BATCH), -1.0f), 1.0f);
        out[0] = -mm
               + 5.0f * (mind * (1.0f / 16777216.0f))
               + 0.1f * (reg * (1.0f / 524288.0f));
        g_done = 0u;   // reset for next graph replay
    }
}

// ---------------- launch ----------------
extern "C" void kernel_launch(void* const* d_in, const int* in_sizes, int n_in,
                              void* d_out, int out_size) {
    const float* fixed = (const float*)d_in[0];
    const float* moved = (const float*)d_in[1];
    const float* flow  = (const float*)d_in[2];
    if (n_in >= 3) {
        int fi = -1;
        for (int i = 0; i < 3; i++) if (in_sizes[i] == 2 * BATCH * HF * HF) fi = i;
        if (fi == 0) { flow = (const float*)d_in[0]; fixed = (const float*)d_in[1]; moved = (const float*)d_in[2]; }
        else if (fi == 1) { fixed = (const float*)d_in[0]; flow = (const float*)d_in[1]; moved = (const float*)d_in[2]; }
    }

    k_main<<<1280, 512>>>(fixed, moved, flow, (float*)d_out);
}